// round 10
// baseline (speedup 1.0000x reference)
#include <cuda_runtime.h>
#include <cstdint>

#define N_NODES 40000
#define N_EDGES 640000
#define DIM 128
#define KC 32            // K chunk staged in smem
#define AST 68           // As row stride (words): 64 + 4 pad
#define WST 132          // Ws row stride (words): 128 + 4 pad

// Scratch (no cudaMalloc allowed)
__device__ float g_y[N_NODES * DIM];      // y = x @ W^T
__device__ float g_aggy[N_NODES * DIM];   // agg_y[d] = sum_{(s->d)} y[s]
__device__ float g_colsum[DIM];
__device__ float g_colsumsq[DIM];

// ---------------------------------------------------------------------------
// K0: zero g_aggy + BN stat accumulators (runs on s1, overlapped with gemm0)
// ---------------------------------------------------------------------------
__global__ void k0z() {
    const int total = N_NODES * DIM / 4;
    float4 z = {0.f, 0.f, 0.f, 0.f};
    for (int idx = blockIdx.x * blockDim.x + threadIdx.x; idx < total;
         idx += gridDim.x * blockDim.x)
        ((float4*)g_aggy)[idx] = z;
    if (blockIdx.x == 0 && threadIdx.x < DIM) {
        g_colsum[threadIdx.x]   = 0.0f;
        g_colsumsq[threadIdx.x] = 0.0f;
    }
}

// ---------------------------------------------------------------------------
// KG: y = x @ W^T for rows [row_base, row_base + 64*gridDim.x)
//     R6-proven conflict-free FFMA tile: 256 thr, 64 rows x 128 cols, KC=32.
// ---------------------------------------------------------------------------
__global__ void __launch_bounds__(256, 3)
kg_gemm(const float* __restrict__ x, const float* __restrict__ Wm, int row_base) {
    __shared__ float As[KC][AST];     // As[k][r]
    __shared__ float Ws[KC][WST];     // Ws[k][n]

    const int tid  = threadIdx.x;
    const int row0 = row_base + blockIdx.x * 64;

    const int wid  = tid >> 5, lane = tid & 31;
    const int wr   = wid & 1,  wc   = wid >> 1;   // warp 2x4
    const int lr   = lane & 7, lc   = lane >> 3;  // lane 8x4
    const int rl   = wr * 32 + lr * 4;            // 4 contiguous rows
    const int cl   = wc * 32 + lc * 4;            // cols cl..cl+3 and cl+16..cl+19

    float acc[4][8];
#pragma unroll
    for (int q = 0; q < 4; q++)
#pragma unroll
        for (int c = 0; c < 8; c++) acc[q][c] = 0.0f;

    for (int kc = 0; kc < DIM; kc += KC) {
        __syncthreads();
        // Stage Ws[k][n] <- W[n][kc+k]
        for (int i = tid; i < 128 * 8; i += 256) {
            int n = i >> 3, kq = i & 7;
            float4 w = __ldg((const float4*)Wm + n * 32 + (kc >> 2) + kq);
            Ws[kq * 4 + 0][n] = w.x;
            Ws[kq * 4 + 1][n] = w.y;
            Ws[kq * 4 + 2][n] = w.z;
            Ws[kq * 4 + 3][n] = w.w;
        }
        // Stage As[k][r] <- x[row0+r][kc+k]
        for (int i = tid; i < 64 * 8; i += 256) {
            int r = i >> 3, kq = i & 7;
            float4 xv = __ldg((const float4*)x + (size_t)(row0 + r) * 32 + (kc >> 2) + kq);
            As[kq * 4 + 0][r] = xv.x;
            As[kq * 4 + 1][r] = xv.y;
            As[kq * 4 + 2][r] = xv.z;
            As[kq * 4 + 3][r] = xv.w;
        }
        __syncthreads();

#pragma unroll
        for (int kk = 0; kk < KC; kk++) {
            float4 av = *(const float4*)&As[kk][rl];
            float4 w0 = *(const float4*)&Ws[kk][cl];
            float4 w1 = *(const float4*)&Ws[kk][cl + 16];
            float a[4] = {av.x, av.y, av.z, av.w};
            float w[8] = {w0.x, w0.y, w0.z, w0.w, w1.x, w1.y, w1.z, w1.w};
#pragma unroll
            for (int q = 0; q < 4; q++)
#pragma unroll
                for (int c = 0; c < 8; c++)
                    acc[q][c] = fmaf(a[q], w[c], acc[q][c]);
        }
    }

#pragma unroll
    for (int q = 0; q < 4; q++) {
        int row = row0 + rl + q;
        float4 o0 = {acc[q][0], acc[q][1], acc[q][2], acc[q][3]};
        float4 o1 = {acc[q][4], acc[q][5], acc[q][6], acc[q][7]};
        *(float4*)&g_y[(size_t)row * DIM + cl]      = o0;
        *(float4*)&g_y[(size_t)row * DIM + cl + 16] = o1;
    }
}

// ---------------------------------------------------------------------------
// KS: y-space edge scatter for src in [lo, hi) — one warp per edge,
//     red.global.add.v4.f32 (proven pattern). agg_y[dst] += y[src].
// ---------------------------------------------------------------------------
__global__ void ks_scatter(const int* __restrict__ ei, int lo, int hi) {
    int warp = (blockIdx.x * blockDim.x + threadIdx.x) >> 5;
    int lane = threadIdx.x & 31;
    if (warp >= N_EDGES) return;
    int src = __ldg(&ei[warp]);
    if (src < lo || src >= hi) return;
    int dst = __ldg(&ei[N_EDGES + warp]);
    float4 v = __ldg((const float4*)g_y + (size_t)src * (DIM / 4) + lane);
    float* dp = g_aggy + (size_t)dst * DIM + lane * 4;
    asm volatile("red.global.add.v4.f32 [%0], {%1, %2, %3, %4};"
                 :: "l"(dp), "f"(v.x), "f"(v.y), "f"(v.z), "f"(v.w)
                 : "memory");
}

// ---------------------------------------------------------------------------
// KT: per-column sum/sumsq of h = (1+eps)*y + agg_y
// ---------------------------------------------------------------------------
__global__ void kt_stats(const float* __restrict__ gin_eps) {
    const int c = threadIdx.x;  // 128 threads = 128 cols
    const float ce = 1.0f + __ldg(gin_eps);
    float s = 0.f, s2 = 0.f;
    for (int r = blockIdx.x; r < N_NODES; r += gridDim.x) {
        float h = fmaf(ce, g_y[(size_t)r * DIM + c], g_aggy[(size_t)r * DIM + c]);
        s += h;
        s2 += h * h;
    }
    atomicAdd(&g_colsum[c], s);
    atomicAdd(&g_colsumsq[c], s2);
}

// ---------------------------------------------------------------------------
// KF: out = relu(gamma*(h-mean)*rsqrt(var+eps)+beta) + x,  h = (1+eps)y + aggy
//     (Linear bias cancels exactly inside BatchNorm -> never materialized.)
// ---------------------------------------------------------------------------
__global__ void kf_final(const float* __restrict__ x,
                         const float* __restrict__ gamma,
                         const float* __restrict__ beta,
                         const float* __restrict__ gin_eps,
                         float* __restrict__ out) {
    __shared__ float sc_s[DIM], sh_s[DIM];
    if (threadIdx.x < DIM) {
        int c = threadIdx.x;
        const float invN = 1.0f / (float)N_NODES;
        float mean = g_colsum[c] * invN;
        float var  = g_colsumsq[c] * invN - mean * mean;
        float inv  = rsqrtf(var + 1e-5f);
        float sc   = __ldg(&gamma[c]) * inv;
        sc_s[c] = sc;
        sh_s[c] = __ldg(&beta[c]) - mean * sc;
    }
    __syncthreads();
    const float ce = 1.0f + __ldg(gin_eps);
    const int total = N_NODES * DIM / 4;
    for (int idx = blockIdx.x * blockDim.x + threadIdx.x; idx < total;
         idx += gridDim.x * blockDim.x) {
        int c4 = (idx & 31) << 2;
        float4 yv = ((const float4*)g_y)[idx];
        float4 gv = ((const float4*)g_aggy)[idx];
        float4 xv = __ldg((const float4*)x + idx);
        float4 sc = *(float4*)&sc_s[c4];
        float4 sh = *(float4*)&sh_s[c4];
        float4 o;
        float h0 = fmaf(ce, yv.x, gv.x);
        float h1 = fmaf(ce, yv.y, gv.y);
        float h2 = fmaf(ce, yv.z, gv.z);
        float h3 = fmaf(ce, yv.w, gv.w);
        o.x = fmaxf(fmaf(h0, sc.x, sh.x), 0.0f) + xv.x;
        o.y = fmaxf(fmaf(h1, sc.y, sh.y), 0.0f) + xv.y;
        o.z = fmaxf(fmaf(h2, sc.z, sh.z), 0.0f) + xv.z;
        o.w = fmaxf(fmaf(h3, sc.w, sh.w), 0.0f) + xv.w;
        ((float4*)out)[idx] = o;
    }
}

// ---------------------------------------------------------------------------
// Launch: fork a second stream during capture so the y-space scatter (LTS-bound)
// overlaps the remaining GEMM chunks (FMA-bound).
//   s0: gemm0 .. gemm3 (events after each), then stats + final after join
//   s1: zero aggy, then scatter chunk c after gemm chunk c's event
// ---------------------------------------------------------------------------
#define NCHUNK 4

extern "C" void kernel_launch(void* const* d_in, const int* in_sizes, int n_in,
                              void* d_out, int out_size) {
    const float* x       = (const float*)d_in[0];
    const int*   ei      = (const int*)d_in[1];
    const float* Wm      = (const float*)d_in[2];
    // d_in[3] = bias: cancels exactly inside BatchNorm -> unused
    const float* gamma   = (const float*)d_in[4];
    const float* beta    = (const float*)d_in[5];
    const float* gin_eps = (const float*)d_in[6];
    float* out = (float*)d_out;

    // 625 row-blocks of 64 split into 4 chunks
    static const int chunk_blocks[NCHUNK] = {160, 160, 160, 145};

    cudaStream_t s1;
    cudaStreamCreateWithFlags(&s1, cudaStreamNonBlocking);
    cudaEvent_t eFork, eJoin, eC[NCHUNK];
    cudaEventCreateWithFlags(&eFork, cudaEventDisableTiming);
    cudaEventCreateWithFlags(&eJoin, cudaEventDisableTiming);
    for (int c = 0; c < NCHUNK; c++)
        cudaEventCreateWithFlags(&eC[c], cudaEventDisableTiming);

    // Fork s1 off the capturing (default) stream
    cudaEventRecord(eFork, 0);
    cudaStreamWaitEvent(s1, eFork, 0);

    // s1: zero agg_y + stats (overlaps gemm chunk 0)
    k0z<<<1184, 256, 0, s1>>>();

    // s0: GEMM chunks
    int base = 0;
    for (int c = 0; c < NCHUNK; c++) {
        kg_gemm<<<chunk_blocks[c], 256>>>(x, Wm, base);
        cudaEventRecord(eC[c], 0);
        base += chunk_blocks[c] * 64;
    }

    // s1: scatter chunks, each gated on its GEMM chunk
    int lo = 0;
    for (int c = 0; c < NCHUNK; c++) {
        int hi = lo + chunk_blocks[c] * 64;
        cudaStreamWaitEvent(s1, eC[c], 0);
        ks_scatter<<<N_EDGES / 8, 256, 0, s1>>>(ei, lo, hi);
        lo = hi;
    }
    cudaEventRecord(eJoin, s1);

    // s0: join, then stats + final
    cudaStreamWaitEvent(0, eJoin, 0);
    kt_stats<<<512, 128>>>(gin_eps);
    kf_final<<<1184, 256>>>(x, gamma, beta, gin_eps, out);

    // NOTE: streams/events deliberately not destroyed here — destroying a
    // forked stream mid-capture invalidates the capture. kernel_launch runs
    // only a handful of times (correctness + capture), so the leaked host
    // objects are bounded and no device memory is allocated.
}

// round 13
// speedup vs baseline: 1.8388x; 1.8388x over previous
#include <cuda_runtime.h>
#include <cstdint>

#define N_NODES 40000
#define N_EDGES 640000
#define DIM 128
#define KC 32            // K chunk staged in smem
#define AST 68           // As row stride (words): 64 + 4 pad
#define WST 132          // Ws row stride (words): 128 + 4 pad

// Scratch (no cudaMalloc allowed). __device__ globals are zero-initialized at
// module load; every kernel_launch execution restores them to zero at its tail
// (k3), so no up-front zeroing kernel is needed on any run or replay.
__device__ float g_agg[N_NODES * DIM];
__device__ float g_h[N_NODES * DIM];
__device__ float g_colsum[DIM];
__device__ float g_colsumsq[DIM];
__device__ unsigned g_done;   // k3 arrival counter (reset by last block)

// ---------------------------------------------------------------------------
// K1: edge scatter — one warp per edge, red.global.add.v4.f32 (proven)
//     agg[dst] += x[src]   (g_agg is zero on entry: static init / prior k3)
// ---------------------------------------------------------------------------
__global__ void k1_scatter(const float* __restrict__ x,
                           const int* __restrict__ ei) {
    int warp = (blockIdx.x * blockDim.x + threadIdx.x) >> 5;
    int lane = threadIdx.x & 31;
    if (warp >= N_EDGES) return;
    int src = __ldg(&ei[warp]);
    int dst = __ldg(&ei[N_EDGES + warp]);
    float4 v = __ldg((const float4*)x + src * (DIM / 4) + lane);
    float* dp = g_agg + (size_t)dst * DIM + lane * 4;
    asm volatile("red.global.add.v4.f32 [%0], {%1, %2, %3, %4};"
                 :: "l"(dp), "f"(v.x), "f"(v.y), "f"(v.z), "f"(v.w)
                 : "memory");
}

// ---------------------------------------------------------------------------
// K2: h = ((1+eps)x + agg) @ W^T, fused per-column sum/sumsq for BN.
//     Bias omitted (cancels exactly inside BatchNorm). R6-proven layout:
//     CTA 256 thr, tile 64 rows x 128 cols, KC=32; warp 2x4, lane 8x4,
//     micro-tile 4x8; conflict-free main-loop smem reads.
// ---------------------------------------------------------------------------
__global__ void __launch_bounds__(256, 3)
k2_gemm(const float* __restrict__ x, const float* __restrict__ Wm,
        const float* __restrict__ gin_eps) {
    __shared__ float As[KC][AST];     // As[k][r]
    __shared__ float Ws[KC][WST];     // Ws[k][n]
    __shared__ float cs[DIM], cs2[DIM];

    const int tid  = threadIdx.x;
    const int row0 = blockIdx.x * 64;             // 625 * 64 == 40000 exactly
    const float ce = 1.0f + __ldg(gin_eps);

    const int wid  = tid >> 5, lane = tid & 31;
    const int wr   = wid & 1,  wc   = wid >> 1;   // warp 2x4
    const int lr   = lane & 7, lc   = lane >> 3;  // lane 8x4
    const int rl   = wr * 32 + lr * 4;            // 4 contiguous rows
    const int cl   = wc * 32 + lc * 4;            // cols cl..cl+3 and cl+16..cl+19

    if (tid < DIM) { cs[tid] = 0.0f; cs2[tid] = 0.0f; }

    float acc[4][8];
#pragma unroll
    for (int q = 0; q < 4; q++)
#pragma unroll
        for (int c = 0; c < 8; c++) acc[q][c] = 0.0f;

    for (int kc = 0; kc < DIM; kc += KC) {
        __syncthreads();
        // Stage Ws[k][n] <- W[n][kc+k]  (transpose, 128 n x 8 float4)
        for (int i = tid; i < 128 * 8; i += 256) {
            int n = i >> 3, kq = i & 7;
            float4 w = __ldg((const float4*)Wm + n * 32 + (kc >> 2) + kq);
            Ws[kq * 4 + 0][n] = w.x;
            Ws[kq * 4 + 1][n] = w.y;
            Ws[kq * 4 + 2][n] = w.z;
            Ws[kq * 4 + 3][n] = w.w;
        }
        // Stage As[k][r] <- (1+eps)*x + agg  (transpose, 64 r x 8 float4)
        for (int i = tid; i < 64 * 8; i += 256) {
            int r = i >> 3, kq = i & 7;
            size_t off = (size_t)(row0 + r) * 32 + (kc >> 2) + kq;
            float4 xv = __ldg((const float4*)x + off);
            float4 gv = *((const float4*)g_agg + off);
            As[kq * 4 + 0][r] = fmaf(ce, xv.x, gv.x);
            As[kq * 4 + 1][r] = fmaf(ce, xv.y, gv.y);
            As[kq * 4 + 2][r] = fmaf(ce, xv.z, gv.z);
            As[kq * 4 + 3][r] = fmaf(ce, xv.w, gv.w);
        }
        __syncthreads();

#pragma unroll
        for (int kk = 0; kk < KC; kk++) {
            float4 av = *(const float4*)&As[kk][rl];
            float4 w0 = *(const float4*)&Ws[kk][cl];
            float4 w1 = *(const float4*)&Ws[kk][cl + 16];
            float a[4] = {av.x, av.y, av.z, av.w};
            float w[8] = {w0.x, w0.y, w0.z, w0.w, w1.x, w1.y, w1.z, w1.w};
#pragma unroll
            for (int q = 0; q < 4; q++)
#pragma unroll
                for (int c = 0; c < 8; c++)
                    acc[q][c] = fmaf(a[q], w[c], acc[q][c]);
        }
    }

    // Epilogue: store h + accumulate per-column sum/sumsq
    float csum[8], csq[8];
#pragma unroll
    for (int c = 0; c < 8; c++) { csum[c] = 0.0f; csq[c] = 0.0f; }

#pragma unroll
    for (int q = 0; q < 4; q++) {
        int row = row0 + rl + q;
        float4 o0 = {acc[q][0], acc[q][1], acc[q][2], acc[q][3]};
        float4 o1 = {acc[q][4], acc[q][5], acc[q][6], acc[q][7]};
        *(float4*)&g_h[(size_t)row * DIM + cl]      = o0;
        *(float4*)&g_h[(size_t)row * DIM + cl + 16] = o1;
#pragma unroll
        for (int c = 0; c < 8; c++) {
            csum[c] += acc[q][c];
            csq[c]  += acc[q][c] * acc[q][c];
        }
    }
#pragma unroll
    for (int c = 0; c < 4; c++) {
        atomicAdd(&cs[cl + c],       csum[c]);
        atomicAdd(&cs[cl + 16 + c],  csum[c + 4]);
        atomicAdd(&cs2[cl + c],      csq[c]);
        atomicAdd(&cs2[cl + 16 + c], csq[c + 4]);
    }
    __syncthreads();
    if (tid < DIM) {
        atomicAdd(&g_colsum[tid],   cs[tid]);
        atomicAdd(&g_colsumsq[tid], cs2[tid]);
    }
}

// ---------------------------------------------------------------------------
// K3: out = relu(gamma*(h-mean)*rsqrt(var+eps)+beta) + x
//     Tail restores the zero-state for the next graph replay:
//       - each block zeroes its grid-stride slice of g_agg (k2 already done)
//       - the LAST block (arrival counter, after every block has copied
//         scale/shift into its smem) zeroes g_colsum/g_colsumsq + counter.
// ---------------------------------------------------------------------------
__global__ void k3_final(const float* __restrict__ x,
                         const float* __restrict__ gamma,
                         const float* __restrict__ beta,
                         float* __restrict__ out) {
    __shared__ float sc_s[DIM], sh_s[DIM];
    __shared__ int lastFlag;
    if (threadIdx.x < DIM) {
        int c = threadIdx.x;
        const float invN = 1.0f / (float)N_NODES;
        float mean = g_colsum[c] * invN;
        float var  = g_colsumsq[c] * invN - mean * mean;
        float inv  = rsqrtf(var + 1e-5f);
        float sc   = __ldg(&gamma[c]) * inv;
        sc_s[c] = sc;
        sh_s[c] = __ldg(&beta[c]) - mean * sc;
    }
    __syncthreads();   // all threads of this block have consumed g_colsum/sumsq

    if (threadIdx.x == 0) {
        unsigned t = atomicAdd(&g_done, 1u);
        lastFlag = (t == gridDim.x - 1u);   // full only after ALL blocks consumed stats
    }
    __syncthreads();
    if (lastFlag) {
        if (threadIdx.x < DIM) {
            g_colsum[threadIdx.x]   = 0.0f;
            g_colsumsq[threadIdx.x] = 0.0f;
        }
        if (threadIdx.x == 0) g_done = 0u;
    }

    const int total = N_NODES * DIM / 4;
    float4 z = {0.f, 0.f, 0.f, 0.f};
    for (int idx = blockIdx.x * blockDim.x + threadIdx.x; idx < total;
         idx += gridDim.x * blockDim.x) {
        int c4 = (idx & 31) << 2;
        float4 h  = ((const float4*)g_h)[idx];
        float4 xv = __ldg((const float4*)x + idx);
        float4 sc = *(float4*)&sc_s[c4];
        float4 sh = *(float4*)&sh_s[c4];
        float4 o;
        o.x = fmaxf(fmaf(h.x, sc.x, sh.x), 0.0f) + xv.x;
        o.y = fmaxf(fmaf(h.y, sc.y, sh.y), 0.0f) + xv.y;
        o.z = fmaxf(fmaf(h.z, sc.z, sh.z), 0.0f) + xv.z;
        o.w = fmaxf(fmaf(h.w, sc.w, sh.w), 0.0f) + xv.w;
        ((float4*)out)[idx] = o;
        ((float4*)g_agg)[idx] = z;     // restore zero for next replay (k2 done)
    }
}

// ---------------------------------------------------------------------------
extern "C" void kernel_launch(void* const* d_in, const int* in_sizes, int n_in,
                              void* d_out, int out_size) {
    const float* x       = (const float*)d_in[0];
    const int*   ei      = (const int*)d_in[1];
    const float* Wm      = (const float*)d_in[2];
    // d_in[3] = bias: cancels exactly inside BatchNorm -> unused
    const float* gamma   = (const float*)d_in[4];
    const float* beta    = (const float*)d_in[5];
    const float* gin_eps = (const float*)d_in[6];
    float* out = (float*)d_out;

    k1_scatter<<<N_EDGES / 8, 256>>>(x, ei);      // 1 warp per edge
    k2_gemm<<<N_NODES / 64, 256>>>(x, Wm, gin_eps);
    k3_final<<<1184, 256>>>(x, gamma, beta, out);
}

// round 15
// speedup vs baseline: 1.9716x; 1.0722x over previous
#include <cuda_runtime.h>
#include <cstdint>

#define N_NODES 40000
#define N_EDGES 640000
#define DIM 128
#define EPW 8            // edges per warp in k1
#define KC 32            // K chunk staged in smem
#define AST 68           // As row stride (words): 64 + 4 pad
#define WST 132          // Ws row stride (words): 128 + 4 pad

// Scratch (no cudaMalloc allowed). __device__ globals are zero-initialized at
// module load; every kernel_launch execution restores them to zero at its tail
// (k3), so no up-front zeroing kernel is needed on any run or replay.
__device__ float g_agg[N_NODES * DIM];
__device__ float g_h[N_NODES * DIM];
__device__ float g_colsum[DIM];
__device__ float g_colsumsq[DIM];
__device__ unsigned g_done;   // k3 arrival counter (reset by last block)

// ---------------------------------------------------------------------------
// K1: edge scatter — EPW edges per warp for MLP=8 latency hiding.
//     agg[dst] += x[src]   (g_agg is zero on entry: static init / prior k3)
// ---------------------------------------------------------------------------
__global__ void __launch_bounds__(256)
k1_scatter(const float* __restrict__ x, const int* __restrict__ ei) {
    const int warp = (blockIdx.x * blockDim.x + threadIdx.x) >> 5;
    const int lane = threadIdx.x & 31;
    const int e0 = warp * EPW;
    if (e0 >= N_EDGES) return;

    // Uniform (warp-broadcast) edge loads: 2x int4 srcs + 2x int4 dsts
    int4 sa = *(const int4*)&ei[e0];
    int4 sb = *(const int4*)&ei[e0 + 4];
    int4 da = *(const int4*)&ei[N_EDGES + e0];
    int4 db = *(const int4*)&ei[N_EDGES + e0 + 4];
    const int src[EPW] = {sa.x, sa.y, sa.z, sa.w, sb.x, sb.y, sb.z, sb.w};
    const int dst[EPW] = {da.x, da.y, da.z, da.w, db.x, db.y, db.z, db.w};

    // Front-batched independent gathers (MLP = EPW)
    float4 v[EPW];
#pragma unroll
    for (int i = 0; i < EPW; i++)
        v[i] = __ldg((const float4*)x + (size_t)src[i] * (DIM / 4) + lane);

#pragma unroll
    for (int i = 0; i < EPW; i++) {
        float* dp = g_agg + (size_t)dst[i] * DIM + lane * 4;
        asm volatile("red.global.add.v4.f32 [%0], {%1, %2, %3, %4};"
                     :: "l"(dp), "f"(v[i].x), "f"(v[i].y), "f"(v[i].z), "f"(v[i].w)
                     : "memory");
    }
}

// ---------------------------------------------------------------------------
// K2: h = ((1+eps)x + agg) @ W^T, fused per-column sum/sumsq for BN.
//     Bias omitted (cancels exactly inside BatchNorm). R6-proven layout:
//     CTA 256 thr, tile 64 rows x 128 cols, KC=32; warp 2x4, lane 8x4,
//     micro-tile 4x8; conflict-free main-loop smem reads. (byte-identical)
// ---------------------------------------------------------------------------
__global__ void __launch_bounds__(256, 3)
k2_gemm(const float* __restrict__ x, const float* __restrict__ Wm,
        const float* __restrict__ gin_eps) {
    __shared__ float As[KC][AST];     // As[k][r]
    __shared__ float Ws[KC][WST];     // Ws[k][n]
    __shared__ float cs[DIM], cs2[DIM];

    const int tid  = threadIdx.x;
    const int row0 = blockIdx.x * 64;             // 625 * 64 == 40000 exactly
    const float ce = 1.0f + __ldg(gin_eps);

    const int wid  = tid >> 5, lane = tid & 31;
    const int wr   = wid & 1,  wc   = wid >> 1;   // warp 2x4
    const int lr   = lane & 7, lc   = lane >> 3;  // lane 8x4
    const int rl   = wr * 32 + lr * 4;            // 4 contiguous rows
    const int cl   = wc * 32 + lc * 4;            // cols cl..cl+3 and cl+16..cl+19

    if (tid < DIM) { cs[tid] = 0.0f; cs2[tid] = 0.0f; }

    float acc[4][8];
#pragma unroll
    for (int q = 0; q < 4; q++)
#pragma unroll
        for (int c = 0; c < 8; c++) acc[q][c] = 0.0f;

    for (int kc = 0; kc < DIM; kc += KC) {
        __syncthreads();
        // Stage Ws[k][n] <- W[n][kc+k]  (transpose, 128 n x 8 float4)
        for (int i = tid; i < 128 * 8; i += 256) {
            int n = i >> 3, kq = i & 7;
            float4 w = __ldg((const float4*)Wm + n * 32 + (kc >> 2) + kq);
            Ws[kq * 4 + 0][n] = w.x;
            Ws[kq * 4 + 1][n] = w.y;
            Ws[kq * 4 + 2][n] = w.z;
            Ws[kq * 4 + 3][n] = w.w;
        }
        // Stage As[k][r] <- (1+eps)*x + agg  (transpose, 64 r x 8 float4)
        for (int i = tid; i < 64 * 8; i += 256) {
            int r = i >> 3, kq = i & 7;
            size_t off = (size_t)(row0 + r) * 32 + (kc >> 2) + kq;
            float4 xv = __ldg((const float4*)x + off);
            float4 gv = *((const float4*)g_agg + off);
            As[kq * 4 + 0][r] = fmaf(ce, xv.x, gv.x);
            As[kq * 4 + 1][r] = fmaf(ce, xv.y, gv.y);
            As[kq * 4 + 2][r] = fmaf(ce, xv.z, gv.z);
            As[kq * 4 + 3][r] = fmaf(ce, xv.w, gv.w);
        }
        __syncthreads();

#pragma unroll
        for (int kk = 0; kk < KC; kk++) {
            float4 av = *(const float4*)&As[kk][rl];
            float4 w0 = *(const float4*)&Ws[kk][cl];
            float4 w1 = *(const float4*)&Ws[kk][cl + 16];
            float a[4] = {av.x, av.y, av.z, av.w};
            float w[8] = {w0.x, w0.y, w0.z, w0.w, w1.x, w1.y, w1.z, w1.w};
#pragma unroll
            for (int q = 0; q < 4; q++)
#pragma unroll
                for (int c = 0; c < 8; c++)
                    acc[q][c] = fmaf(a[q], w[c], acc[q][c]);
        }
    }

    // Epilogue: store h + accumulate per-column sum/sumsq
    float csum[8], csq[8];
#pragma unroll
    for (int c = 0; c < 8; c++) { csum[c] = 0.0f; csq[c] = 0.0f; }

#pragma unroll
    for (int q = 0; q < 4; q++) {
        int row = row0 + rl + q;
        float4 o0 = {acc[q][0], acc[q][1], acc[q][2], acc[q][3]};
        float4 o1 = {acc[q][4], acc[q][5], acc[q][6], acc[q][7]};
        *(float4*)&g_h[(size_t)row * DIM + cl]      = o0;
        *(float4*)&g_h[(size_t)row * DIM + cl + 16] = o1;
#pragma unroll
        for (int c = 0; c < 8; c++) {
            csum[c] += acc[q][c];
            csq[c]  += acc[q][c] * acc[q][c];
        }
    }
#pragma unroll
    for (int c = 0; c < 4; c++) {
        atomicAdd(&cs[cl + c],       csum[c]);
        atomicAdd(&cs[cl + 16 + c],  csum[c + 4]);
        atomicAdd(&cs2[cl + c],      csq[c]);
        atomicAdd(&cs2[cl + 16 + c], csq[c + 4]);
    }
    __syncthreads();
    if (tid < DIM) {
        atomicAdd(&g_colsum[tid],   cs[tid]);
        atomicAdd(&g_colsumsq[tid], cs2[tid]);
    }
}

// ---------------------------------------------------------------------------
// K3: out = relu(gamma*(h-mean)*rsqrt(var+eps)+beta) + x
//     Tail restores zero-state for the next graph replay (proven in R10-13):
//       - each block zeroes its grid-stride slice of g_agg
//       - last-arriving block zeroes g_colsum/g_colsumsq + counter
// ---------------------------------------------------------------------------
__global__ void k3_final(const float* __restrict__ x,
                         const float* __restrict__ gamma,
                         const float* __restrict__ beta,
                         float* __restrict__ out) {
    __shared__ float sc_s[DIM], sh_s[DIM];
    __shared__ int lastFlag;
    if (threadIdx.x < DIM) {
        int c = threadIdx.x;
        const float invN = 1.0f / (float)N_NODES;
        float mean = g_colsum[c] * invN;
        float var  = g_colsumsq[c] * invN - mean * mean;
        float inv  = rsqrtf(var + 1e-5f);
        float sc   = __ldg(&gamma[c]) * inv;
        sc_s[c] = sc;
        sh_s[c] = __ldg(&beta[c]) - mean * sc;
    }
    __syncthreads();   // all threads of this block have consumed g_colsum/sumsq

    if (threadIdx.x == 0) {
        unsigned t = atomicAdd(&g_done, 1u);
        lastFlag = (t == gridDim.x - 1u);
    }
    __syncthreads();
    if (lastFlag) {
        if (threadIdx.x < DIM) {
            g_colsum[threadIdx.x]   = 0.0f;
            g_colsumsq[threadIdx.x] = 0.0f;
        }
        if (threadIdx.x == 0) g_done = 0u;
    }

    const int total = N_NODES * DIM / 4;
    float4 z = {0.f, 0.f, 0.f, 0.f};
    for (int idx = blockIdx.x * blockDim.x + threadIdx.x; idx < total;
         idx += gridDim.x * blockDim.x) {
        int c4 = (idx & 31) << 2;
        float4 h  = ((const float4*)g_h)[idx];
        float4 xv = __ldg((const float4*)x + idx);
        float4 sc = *(float4*)&sc_s[c4];
        float4 sh = *(float4*)&sh_s[c4];
        float4 o;
        o.x = fmaxf(fmaf(h.x, sc.x, sh.x), 0.0f) + xv.x;
        o.y = fmaxf(fmaf(h.y, sc.y, sh.y), 0.0f) + xv.y;
        o.z = fmaxf(fmaf(h.z, sc.z, sh.z), 0.0f) + xv.z;
        o.w = fmaxf(fmaf(h.w, sc.w, sh.w), 0.0f) + xv.w;
        ((float4*)out)[idx] = o;
        ((float4*)g_agg)[idx] = z;     // restore zero for next replay (k2 done)
    }
}

// ---------------------------------------------------------------------------
extern "C" void kernel_launch(void* const* d_in, const int* in_sizes, int n_in,
                              void* d_out, int out_size) {
    const float* x       = (const float*)d_in[0];
    const int*   ei      = (const int*)d_in[1];
    const float* Wm      = (const float*)d_in[2];
    // d_in[3] = bias: cancels exactly inside BatchNorm -> unused
    const float* gamma   = (const float*)d_in[4];
    const float* beta    = (const float*)d_in[5];
    const float* gin_eps = (const float*)d_in[6];
    float* out = (float*)d_out;

    // 640000 edges / 8 per warp = 80000 warps = 10000 blocks of 256
    k1_scatter<<<N_EDGES / (EPW * 8), 256>>>(x, ei);
    k2_gemm<<<N_NODES / 64, 256>>>(x, Wm, gin_eps);
    k3_final<<<1184, 256>>>(x, gamma, beta, out);
}